// round 13
// baseline (speedup 1.0000x reference)
#include <cuda_runtime.h>

#define LDIM 16
#define CDIM 16
#define WID 128
#define BATCH 2048
#define NSTEPS 8
#define NT 17            // distinct t values: 1 - k/16, k=0..16
#define SPB 16           // samples per block
#define NTH 256
#define LOG2PI_F 1.8378770664093453f

typedef unsigned long long u64;

// Precomputed per-t tables (prep kernel fills these every launch)
// g_WE2[m][p][i] = ( W1_1[i][2p], E0_m[i][2p], W1_1[i][2p+1], E0_m[i][2p+1] )
// E0_m[i][j] = W1_1[i][j]*P_m[j][i]*g0_m[j]
// P_m[j][i] = sum_k W1_0[j][k]*g2_m[k]*W1_2[k][i]
// g_Es[m][i] = sum_j E0_m[i][j]
__device__ float4 g_WE2[NT][WID / 2][WID];
__device__ float  g_Es[NT][WID];
__device__ float g_g0[NT][WID], g_be0[NT][WID];
__device__ float g_g1[NT][WID], g_be1[NT][WID];
__device__ float g_g2[NT][LDIM], g_be2[NT][LDIM];

__device__ __forceinline__ float sigmoidf_(float x) {
    return __fdividef(1.0f, 1.0f + __expf(-x));
}
__device__ __forceinline__ float tanhf_(float x) {
    return 1.0f - __fdividef(2.0f, __expf(2.0f * x) + 1.0f);
}
__device__ __forceinline__ u64 pack2_(float lo, float hi) {
    u64 r; asm("mov.b64 %0, {%1, %2};" : "=l"(r) : "f"(lo), "f"(hi)); return r;
}
__device__ __forceinline__ void unpack2_(u64 v, float& lo, float& hi) {
    asm("mov.b64 {%0, %1}, %2;" : "=f"(lo), "=f"(hi) : "l"(v));
}
__device__ __forceinline__ void ffma2_(u64& d, u64 a, u64 b) {
    asm("fma.rn.f32x2 %0, %1, %2, %0;" : "+l"(d) : "l"(a), "l"(b));
}
__device__ __forceinline__ void fmul2_(u64& d, u64 a, u64 b) {
    asm("mul.rn.f32x2 %0, %1, %2;" : "=l"(d) : "l"(a), "l"(b));
}

// ---------------------------------------------------------------------------
// Setup kernel: 1024 threads, thread (i = tid&127, jc = tid>>7) computes
// 16 consecutive j's (8 pairs). es reduced via smem partials.
// ---------------------------------------------------------------------------
__global__ void prep_kernel(
    const float* __restrict__ W1_0, const float* __restrict__ b1_0,
    const float* __restrict__ W2_0, const float* __restrict__ b2_0,
    const float* __restrict__ W3_0,
    const float* __restrict__ W1_1, const float* __restrict__ b1_1,
    const float* __restrict__ W2_1, const float* __restrict__ b2_1,
    const float* __restrict__ W3_1,
    const float* __restrict__ W1_2, const float* __restrict__ b1_2,
    const float* __restrict__ W2_2, const float* __restrict__ b2_2,
    const float* __restrict__ W3_2)
{
    const int m  = blockIdx.x;
    const int tid = threadIdx.x;
    const int i  = tid & 127;
    const int jc = tid >> 7;          // 0..7
    const float t = 1.0f - 0.0625f * (float)m;

    __shared__ float sg0[WID], sg2[LDIM];
    __shared__ float esp[8][WID];

    if (jc == 0) {
        float g = sigmoidf_(W2_0[i] * t + b2_0[i]);
        sg0[i] = g;
        g_g0[m][i] = g;
        g_be0[m][i] = g * b1_0[i] + t * W3_0[i];

        float h = sigmoidf_(W2_1[i] * t + b2_1[i]);
        g_g1[m][i] = h;
        g_be1[m][i] = h * b1_1[i] + t * W3_1[i];

        if (i < LDIM) {
            float g2 = sigmoidf_(W2_2[i] * t + b2_2[i]);
            sg2[i] = g2;
            g_g2[m][i] = g2;
            g_be2[m][i] = g2 * b1_2[i] + t * W3_2[i];
        }
    }
    __syncthreads();

    float a[LDIM];
#pragma unroll
    for (int k = 0; k < LDIM; k++) a[k] = sg2[k] * W1_2[k * WID + i];

    float es = 0.0f;
#pragma unroll
    for (int pp = 0; pp < 8; pp++) {
        const int p = jc * 8 + pp;
        float w[2], e[2];
#pragma unroll
        for (int r = 0; r < 2; r++) {
            const int j = 2 * p + r;
            float q = 0.0f;
#pragma unroll
            for (int k = 0; k < LDIM; k++)
                q += W1_0[j * (LDIM + CDIM) + k] * a[k];
            w[r] = W1_1[i * WID + j];
            e[r] = w[r] * q * sg0[j];
            es += e[r];
        }
        g_WE2[m][p][i] = make_float4(w[0], e[0], w[1], e[1]);
    }
    esp[jc][i] = es;
    __syncthreads();
    if (jc == 0) {
        float s = 0.0f;
#pragma unroll
        for (int c = 0; c < 8; c++) s += esp[c][i];
        g_Es[m][i] = s;
    }
}

// ---------------------------------------------------------------------------
// Main kernel: 256 threads, 16 samples/block, 2 CTAs co-resident per SM.
// Table traffic amortized over 16 samples. Layer 1 split-j: warp =
// (nb = w&3, jp = w>>2, 64 j each); thread accumulates ALL 16 samples.
// Thread (i = tid&127, hs = tid>>7) owns q groups {2hs, 2hs+1} elsewhere.
// ---------------------------------------------------------------------------
struct SM {
    float Wt0y[LDIM][WID];         // [j][i] = W1_0[i][j], y-part
    float Wt2[WID][LDIM];          // [i][k] = W1_2[k][i]
    float x  [4][LDIM * 4];        // stage input (y part), [q][j*4+c]
    float h1 [4][WID * 4];         // [q][i*4+c]
    float h2 [4][WID * 4];
    u64 predA[2][8][WID];          // [jp][sample-pair][i] partial W-acc
    u64 predB[2][8][WID];          // [jp][sample-pair][i] partial E*h^2-acc
    float yb[LDIM][SPB + 2];
    float ya[LDIM][SPB + 2];
    float dlp[SPB];
    float wred[8][8];
};

__global__ void __launch_bounds__(NTH, 2)
cnf_kernel(const float* __restrict__ z, const float* __restrict__ cond,
           const float* __restrict__ W1_0, const float* __restrict__ W1_2,
           float* __restrict__ out)
{
    extern __shared__ float smraw[];
    SM* sm = reinterpret_cast<SM*>(smraw);
    const int tid  = threadIdx.x;
    const int lane = tid & 31;
    const int wrp  = tid >> 5;
    const int i    = tid & 127;       // neuron (layer0 / reduce mapping)
    const int hs   = tid >> 7;        // sample half: q groups {2hs, 2hs+1}
    const int nb   = wrp & 3;         // layer-1 neuron block
    const int jp   = wrp >> 2;        // layer-1 j partition (0..1, 64 j each)
    const int il1  = nb * 32 + lane;  // layer-1 neuron
    const int s0   = blockIdx.x * SPB;

    // --- weights into smem ---
    for (int idx = tid; idx < WID * LDIM; idx += NTH) {
        int r = idx >> 4, j = idx & 15;
        sm->Wt0y[j][r] = W1_0[r * (LDIM + CDIM) + j];
    }
    for (int idx = tid; idx < LDIM * WID; idx += NTH) {
        int k = idx >> 7, r = idx & 127;
        sm->Wt2[r][k] = W1_2[idx];
    }
    // --- per-sample state + initial stage input (t=1: x = z) ---
    {
        int s = tid >> 4, l = tid & 15;       // 256 = SPB*LDIM
        float zv = z[(s0 + s) * LDIM + l];
        sm->yb[l][s] = zv;
        sm->ya[l][s] = 0.0f;
        sm->x[s >> 2][l * 4 + (s & 3)] = zv;
    }
    if (tid < SPB) sm->dlp[tid] = 0.0f;

    // --- stage-invariant condition terms for 8 samples, kept in registers --
    float cacc[8];
#pragma unroll
    for (int c = 0; c < 8; c++) cacc[c] = 0.0f;
#pragma unroll 4
    for (int c = 0; c < CDIM; c++) {
        float w = __ldg(&W1_0[i * (LDIM + CDIM) + LDIM + c]);
#pragma unroll
        for (int sl = 0; sl < 8; sl++)
            cacc[sl] += w * __ldg(&cond[(s0 + hs * 8 + sl) * CDIM + c]);
    }
    u64 ct[4];
#pragma unroll
    for (int p = 0; p < 4; p++) ct[p] = pack2_(cacc[2 * p], cacc[2 * p + 1]);
    __syncthreads();

    const float dt  = -0.125f;
    const float dt6 = dt * (1.0f / 6.0f);

    for (int e = 0; e < 4 * NSTEPS; e++) {
        const int step = e >> 2, st = e & 3;
        const int   m   = 2 * step + ((st == 0) ? 0 : ((st == 3) ? 2 : 1));
        const float wst = (st == 1 || st == 2) ? 2.0f : 1.0f;

        // --- prefetch first table pairs for this stage ---
        const float4* wep = &g_WE2[m][jp * 32][il1];
        float4 bufA[2], bufB[2];
        bufA[0] = __ldg(wep);
        bufA[1] = __ldg(wep + WID);

        // ----- layer 0: 16 y-cols (+ cached cond), 8 samples/thread --------
        {
            u64 a0 = ct[0], a1 = ct[1], a2 = ct[2], a3 = ct[3];
#pragma unroll
            for (int j = 0; j < LDIM; j++) {
                float w = sm->Wt0y[j][i];
                u64 w2 = pack2_(w, w);
                const ulonglong2 xv0 =
                    *reinterpret_cast<const ulonglong2*>(&sm->x[2 * hs][j * 4]);
                const ulonglong2 xv1 =
                    *reinterpret_cast<const ulonglong2*>(&sm->x[2 * hs + 1][j * 4]);
                ffma2_(a0, w2, xv0.x);
                ffma2_(a1, w2, xv0.y);
                ffma2_(a2, w2, xv1.x);
                ffma2_(a3, w2, xv1.y);
            }
            const float g = g_g0[m][i], be = g_be0[m][i];
            float v[8], h;
            unpack2_(a0, v[0], v[1]);
            unpack2_(a1, v[2], v[3]);
            unpack2_(a2, v[4], v[5]);
            unpack2_(a3, v[6], v[7]);
            float4 hv0, hv1;
            h = tanhf_(g * v[0] + be); hv0.x = h;
            h = tanhf_(g * v[1] + be); hv0.y = h;
            h = tanhf_(g * v[2] + be); hv0.z = h;
            h = tanhf_(g * v[3] + be); hv0.w = h;
            h = tanhf_(g * v[4] + be); hv1.x = h;
            h = tanhf_(g * v[5] + be); hv1.y = h;
            h = tanhf_(g * v[6] + be); hv1.z = h;
            h = tanhf_(g * v[7] + be); hv1.w = h;
            *reinterpret_cast<float4*>(&sm->h1[2 * hs][i * 4]) = hv0;
            *reinterpret_cast<float4*>(&sm->h1[2 * hs + 1][i * 4]) = hv1;
        }
        __syncthreads();

        // ----- layer 1 split-j: all 16 samples over 64 j's -----------------
        {
            u64 a[8], b[8];
#pragma unroll
            for (int pr = 0; pr < 8; pr++) { a[pr] = 0ull; b[pr] = 0ull; }

#pragma unroll 1
            for (int g4 = 0; g4 < 8; g4++) {
                const int pb = g4 * 4;        // pair base within warp's range
                bufB[0] = __ldg(wep + (pb + 2) * WID);
                bufB[1] = __ldg(wep + (pb + 3) * WID);
#pragma unroll
                for (int pp = 0; pp < 2; pp++) {
                    const int j0 = jp * 64 + (pb + pp) * 2;
                    const float4 we = bufA[pp];
                    u64 w2a = pack2_(we.x, we.x), e2a = pack2_(we.y, we.y);
                    u64 w2b = pack2_(we.z, we.z), e2b = pack2_(we.w, we.w);
#pragma unroll
                    for (int q = 0; q < 4; q++) {
                        const ulonglong2 hva =
                            *reinterpret_cast<const ulonglong2*>(&sm->h1[q][j0 * 4]);
                        const ulonglong2 hvb =
                            *reinterpret_cast<const ulonglong2*>(&sm->h1[q][(j0 + 1) * 4]);
                        u64 s0v, s1v;
                        ffma2_(a[2 * q + 0], w2a, hva.x);
                        ffma2_(a[2 * q + 1], w2a, hva.y);
                        fmul2_(s0v, hva.x, hva.x);
                        fmul2_(s1v, hva.y, hva.y);
                        ffma2_(b[2 * q + 0], e2a, s0v);
                        ffma2_(b[2 * q + 1], e2a, s1v);
                        ffma2_(a[2 * q + 0], w2b, hvb.x);
                        ffma2_(a[2 * q + 1], w2b, hvb.y);
                        fmul2_(s0v, hvb.x, hvb.x);
                        fmul2_(s1v, hvb.y, hvb.y);
                        ffma2_(b[2 * q + 0], e2b, s0v);
                        ffma2_(b[2 * q + 1], e2b, s1v);
                    }
                }
                if (g4 < 7) {
                    bufA[0] = __ldg(wep + (pb + 4) * WID);
                    bufA[1] = __ldg(wep + (pb + 5) * WID);
                }
#pragma unroll
                for (int pp = 0; pp < 2; pp++) {
                    const int j0 = jp * 64 + (pb + 2 + pp) * 2;
                    const float4 we = bufB[pp];
                    u64 w2a = pack2_(we.x, we.x), e2a = pack2_(we.y, we.y);
                    u64 w2b = pack2_(we.z, we.z), e2b = pack2_(we.w, we.w);
#pragma unroll
                    for (int q = 0; q < 4; q++) {
                        const ulonglong2 hva =
                            *reinterpret_cast<const ulonglong2*>(&sm->h1[q][j0 * 4]);
                        const ulonglong2 hvb =
                            *reinterpret_cast<const ulonglong2*>(&sm->h1[q][(j0 + 1) * 4]);
                        u64 s0v, s1v;
                        ffma2_(a[2 * q + 0], w2a, hva.x);
                        ffma2_(a[2 * q + 1], w2a, hva.y);
                        fmul2_(s0v, hva.x, hva.x);
                        fmul2_(s1v, hva.y, hva.y);
                        ffma2_(b[2 * q + 0], e2a, s0v);
                        ffma2_(b[2 * q + 1], e2a, s1v);
                        ffma2_(a[2 * q + 0], w2b, hvb.x);
                        ffma2_(a[2 * q + 1], w2b, hvb.y);
                        fmul2_(s0v, hvb.x, hvb.x);
                        fmul2_(s1v, hvb.y, hvb.y);
                        ffma2_(b[2 * q + 0], e2b, s0v);
                        ffma2_(b[2 * q + 1], e2b, s1v);
                    }
                }
            }
            // store partials (disjoint per warp)
#pragma unroll
            for (int pr = 0; pr < 8; pr++) {
                sm->predA[jp][pr][il1] = a[pr];
                sm->predB[jp][pr][il1] = b[pr];
            }
        }
        __syncthreads();

        // ----- reduce partitions; tanh; divergence; write h2 ---------------
        {
            float av[8], bv[8];
#pragma unroll
            for (int c = 0; c < 8; c++) { av[c] = 0.0f; bv[c] = 0.0f; }
#pragma unroll
            for (int p = 0; p < 2; p++) {
#pragma unroll
                for (int pr = 0; pr < 4; pr++) {
                    float x0, x1;
                    unpack2_(sm->predA[p][4 * hs + pr][i], x0, x1);
                    av[2 * pr] += x0; av[2 * pr + 1] += x1;
                    unpack2_(sm->predB[p][4 * hs + pr][i], x0, x1);
                    bv[2 * pr] += x0; bv[2 * pr + 1] += x1;
                }
            }
            const float g  = g_g1[m][i], be = g_be1[m][i];
            const float es = __ldg(&g_Es[m][i]);
            float4 hv0, hv1;
            float vdiv[8];
#pragma unroll
            for (int c = 0; c < 8; c++) {
                float h = tanhf_(g * av[c] + be);
                if (c < 4) ((float*)&hv0)[c] = h;
                else       ((float*)&hv1)[c - 4] = h;
                vdiv[c] = g * (1.0f - h * h) * (es - bv[c]);
            }
            *reinterpret_cast<float4*>(&sm->h2[2 * hs][i * 4]) = hv0;
            *reinterpret_cast<float4*>(&sm->h2[2 * hs + 1][i * 4]) = hv1;
#pragma unroll
            for (int c = 0; c < 8; c++) {
                float r = vdiv[c];
                r += __shfl_xor_sync(0xffffffffu, r, 16);
                r += __shfl_xor_sync(0xffffffffu, r, 8);
                r += __shfl_xor_sync(0xffffffffu, r, 4);
                r += __shfl_xor_sync(0xffffffffu, r, 2);
                r += __shfl_xor_sync(0xffffffffu, r, 1);
                if (lane == 0) sm->wred[wrp][c] = r;
            }
        }
        __syncthreads();

        // ----- layer 2 (128->16): 8 warps, one packed sample pair each -----
        {
            const int sp = wrp;               // sample pair s = 2sp, 2sp+1
            const int k  = lane & 15;
            const int pa = lane >> 4;         // i2 parity
            const int q  = sp >> 1;
            const int cp = sp & 1;
            u64 acc0 = 0ull, acc1 = 0ull;
#pragma unroll 8
            for (int n = 0; n < 64; n += 2) {
                int i2a = 2 * n + pa;
                int i2b = 2 * n + 2 + pa;
                float wa = sm->Wt2[i2a][k];
                float wb = sm->Wt2[i2b][k];
                u64 ha = *reinterpret_cast<const u64*>(&sm->h2[q][i2a * 4 + 2 * cp]);
                u64 hb = *reinterpret_cast<const u64*>(&sm->h2[q][i2b * 4 + 2 * cp]);
                ffma2_(acc0, pack2_(wa, wa), ha);
                ffma2_(acc1, pack2_(wb, wb), hb);
            }
            float l0, h0, l1, h1;
            unpack2_(acc0, l0, h0);
            unpack2_(acc1, l1, h1);
            float flo = l0 + l1, fhi = h0 + h1;
            flo += __shfl_xor_sync(0xffffffffu, flo, 16);
            fhi += __shfl_xor_sync(0xffffffffu, fhi, 16);
            if (lane < 16) {
                const float g = g_g2[m][k], be = g_be2[m][k];
                float f0 = g * flo + be;
                float f1 = g * fhi + be;
                const int s = 2 * sp;
                float2* yap = reinterpret_cast<float2*>(&sm->ya[k][s]);
                float2* ybp = reinterpret_cast<float2*>(&sm->yb[k][s]);
                float2 yav = *yap;
                float2 ybv = *ybp;
                yav.x += wst * f0; yav.y += wst * f1;
                if (st < 3) {
                    *yap = yav;
                    float cn = (st == 2) ? dt : 0.5f * dt;
                    float2 xv = make_float2(ybv.x + cn * f0, ybv.y + cn * f1);
                    *reinterpret_cast<float2*>(&sm->x[q][k * 4 + 2 * cp]) = xv;
                } else {
                    ybv.x += dt6 * yav.x; ybv.y += dt6 * yav.y;
                    *ybp = ybv;
                    *yap = make_float2(0.0f, 0.0f);
                    *reinterpret_cast<float2*>(&sm->x[q][k * 4 + 2 * cp]) = ybv;
                }
            } else if (wrp == 0) {
                // warp 0 lanes 16-31: dlp update for the 16 samples
                const int s = lane - 16;
                const int hb = (s >> 3) * 4, ls = s & 7;
                float dv = sm->wred[hb + 0][ls] + sm->wred[hb + 1][ls] +
                           sm->wred[hb + 2][ls] + sm->wred[hb + 3][ls];
                sm->dlp[s] += dt6 * wst * dv;
            }
        }
        __syncthreads();
    }

    // out = delta_logp + sum(-0.5 y^2 - 0.5 log(2pi))
    if (tid < SPB) {
        const int s = tid;
        float o = sm->dlp[s];
#pragma unroll
        for (int l = 0; l < LDIM; l++) {
            float yv = sm->yb[l][s];
            o += -0.5f * yv * yv - 0.5f * LOG2PI_F;
        }
        out[s0 + s] = o;
    }
}

// ---------------------------------------------------------------------------
extern "C" void kernel_launch(void* const* d_in, const int* in_sizes, int n_in,
                              void* d_out, int out_size)
{
    (void)in_sizes; (void)n_in; (void)out_size;
    const float* W1_0 = (const float*)d_in[0];
    const float* b1_0 = (const float*)d_in[1];
    const float* W2_0 = (const float*)d_in[2];
    const float* b2_0 = (const float*)d_in[3];
    const float* W3_0 = (const float*)d_in[4];
    const float* W1_1 = (const float*)d_in[5];
    const float* b1_1 = (const float*)d_in[6];
    const float* W2_1 = (const float*)d_in[7];
    const float* b2_1 = (const float*)d_in[8];
    const float* W3_1 = (const float*)d_in[9];
    const float* W1_2 = (const float*)d_in[10];
    const float* b1_2 = (const float*)d_in[11];
    const float* W2_2 = (const float*)d_in[12];
    const float* b2_2 = (const float*)d_in[13];
    const float* W3_2 = (const float*)d_in[14];
    const float* z    = (const float*)d_in[15];
    const float* cnd  = (const float*)d_in[16];
    float* out = (float*)d_out;

    cudaFuncSetAttribute(cnf_kernel, cudaFuncAttributeMaxDynamicSharedMemorySize,
                         (int)sizeof(SM));

    prep_kernel<<<NT, 1024>>>(W1_0, b1_0, W2_0, b2_0, W3_0,
                              W1_1, b1_1, W2_1, b2_1, W3_1,
                              W1_2, b1_2, W2_2, b2_2, W3_2);

    cnf_kernel<<<BATCH / SPB, NTH, sizeof(SM)>>>(z, cnd, W1_0, W1_2, out);
}

// round 16
// speedup vs baseline: 1.1585x; 1.1585x over previous
#include <cuda_runtime.h>

#define LDIM 16
#define CDIM 16
#define WID 128
#define BATCH 2048
#define NSTEPS 8
#define NT 17            // distinct t values: 1 - k/16, k=0..16
#define SPB 8            // samples per block
#define NTH 256
#define LOG2PI_F 1.8378770664093453f

typedef unsigned long long u64;

// Precomputed per-t tables (prep kernel fills these every launch)
// g_WE2[m][p][i] = ( W1_1[i][2p], E0_m[i][2p], W1_1[i][2p+1], E0_m[i][2p+1] )
// E0_m[i][j] = W1_1[i][j]*P_m[j][i]*g0_m[j]
// P_m[j][i] = sum_k W1_0[j][k]*g2_m[k]*W1_2[k][i]
// g_Es[m][i] = sum_j E0_m[i][j]
__device__ float4 g_WE2[NT][WID / 2][WID];
__device__ float  g_Es[NT][WID];
__device__ float g_g0[NT][WID], g_be0[NT][WID];
__device__ float g_g1[NT][WID], g_be1[NT][WID];
__device__ float g_g2[NT][LDIM], g_be2[NT][LDIM];

__device__ __forceinline__ float sigmoidf_(float x) {
    return __fdividef(1.0f, 1.0f + __expf(-x));
}
__device__ __forceinline__ float tanhf_(float x) {
    return 1.0f - __fdividef(2.0f, __expf(2.0f * x) + 1.0f);
}
__device__ __forceinline__ u64 pack2_(float lo, float hi) {
    u64 r; asm("mov.b64 %0, {%1, %2};" : "=l"(r) : "f"(lo), "f"(hi)); return r;
}
__device__ __forceinline__ void unpack2_(u64 v, float& lo, float& hi) {
    asm("mov.b64 {%0, %1}, %2;" : "=f"(lo), "=f"(hi) : "l"(v));
}
__device__ __forceinline__ void ffma2_(u64& d, u64 a, u64 b) {
    asm("fma.rn.f32x2 %0, %1, %2, %0;" : "+l"(d) : "l"(a), "l"(b));
}
__device__ __forceinline__ void fmul2_(u64& d, u64 a, u64 b) {
    asm("mul.rn.f32x2 %0, %1, %2;" : "=l"(d) : "l"(a), "l"(b));
}

// ---------------------------------------------------------------------------
// Setup kernel: 1024 threads, thread (i = tid&127, jc = tid>>7) computes
// 16 consecutive j's (8 pairs). es reduced via smem partials.
// ---------------------------------------------------------------------------
__global__ void prep_kernel(
    const float* __restrict__ W1_0, const float* __restrict__ b1_0,
    const float* __restrict__ W2_0, const float* __restrict__ b2_0,
    const float* __restrict__ W3_0,
    const float* __restrict__ W1_1, const float* __restrict__ b1_1,
    const float* __restrict__ W2_1, const float* __restrict__ b2_1,
    const float* __restrict__ W3_1,
    const float* __restrict__ W1_2, const float* __restrict__ b1_2,
    const float* __restrict__ W2_2, const float* __restrict__ b2_2,
    const float* __restrict__ W3_2)
{
    const int m  = blockIdx.x;
    const int tid = threadIdx.x;
    const int i  = tid & 127;
    const int jc = tid >> 7;          // 0..7
    const float t = 1.0f - 0.0625f * (float)m;

    __shared__ float sg0[WID], sg2[LDIM];
    __shared__ float esp[8][WID];

    if (jc == 0) {
        float g = sigmoidf_(W2_0[i] * t + b2_0[i]);
        sg0[i] = g;
        g_g0[m][i] = g;
        g_be0[m][i] = g * b1_0[i] + t * W3_0[i];

        float h = sigmoidf_(W2_1[i] * t + b2_1[i]);
        g_g1[m][i] = h;
        g_be1[m][i] = h * b1_1[i] + t * W3_1[i];

        if (i < LDIM) {
            float g2 = sigmoidf_(W2_2[i] * t + b2_2[i]);
            sg2[i] = g2;
            g_g2[m][i] = g2;
            g_be2[m][i] = g2 * b1_2[i] + t * W3_2[i];
        }
    }
    __syncthreads();

    float a[LDIM];
#pragma unroll
    for (int k = 0; k < LDIM; k++) a[k] = sg2[k] * W1_2[k * WID + i];

    float es = 0.0f;
#pragma unroll
    for (int pp = 0; pp < 8; pp++) {
        const int p = jc * 8 + pp;
        float w[2], e[2];
#pragma unroll
        for (int r = 0; r < 2; r++) {
            const int j = 2 * p + r;
            float q = 0.0f;
#pragma unroll
            for (int k = 0; k < LDIM; k++)
                q += W1_0[j * (LDIM + CDIM) + k] * a[k];
            w[r] = W1_1[i * WID + j];
            e[r] = w[r] * q * sg0[j];
            es += e[r];
        }
        g_WE2[m][p][i] = make_float4(w[0], e[0], w[1], e[1]);
    }
    esp[jc][i] = es;
    __syncthreads();
    if (jc == 0) {
        float s = 0.0f;
#pragma unroll
        for (int c = 0; c < 8; c++) s += esp[c][i];
        g_Es[m][i] = s;
    }
}

// ---------------------------------------------------------------------------
// Main kernel: 256 threads, 8 samples/block, 2 CTAs co-resident per SM.
// Layer 1 split-j: warp = (nb = w&1, jp = w>>1, 32 j each); each lane
// handles 2 neurons (il1, il1+32) so h1 broadcasts are shared and h^2 is
// computed once per (j, sample-quad). Partials reduced across 4 jp's.
// ---------------------------------------------------------------------------
struct SM {
    float Wt0y[LDIM][WID];         // [j][i] = W1_0[i][j], y-part
    float Wt2[WID][LDIM];          // [i][k] = W1_2[k][i]
    float x  [2][LDIM * 4];        // stage input (y part), [q][j*4+c]
    float h1 [2][WID * 4];         // [q][i*4+c]
    float h2 [2][WID * 4];
    u64 predA[4][4][WID];          // [jp][sample-pair][i] partial W-acc
    u64 predB[4][4][WID];          // [jp][sample-pair][i] partial E*h^2-acc
    float yb[LDIM][SPB + 2];
    float ya[LDIM][SPB + 2];
    float dlp[SPB];
    float wred[8][4];
};

// process one pair-row (j0 = 2*pg) for two neurons given their float4 rows
#define L1_PAIR(wea, web, pg)                                                \
    do {                                                                     \
        const int j0 = 2 * (pg);                                             \
        u64 wj0a = pack2_((wea).x, (wea).x), ej0a = pack2_((wea).y, (wea).y);\
        u64 wj1a = pack2_((wea).z, (wea).z), ej1a = pack2_((wea).w, (wea).w);\
        u64 wj0b = pack2_((web).x, (web).x), ej0b = pack2_((web).y, (web).y);\
        u64 wj1b = pack2_((web).z, (web).z), ej1b = pack2_((web).w, (web).w);\
        _Pragma("unroll")                                                    \
        for (int q = 0; q < 2; q++) {                                        \
            const ulonglong2 hva =                                           \
                *reinterpret_cast<const ulonglong2*>(&sm->h1[q][j0 * 4]);    \
            const ulonglong2 hvb =                                           \
                *reinterpret_cast<const ulonglong2*>(&sm->h1[q][(j0 + 1) * 4]);\
            u64 s0, s1, s2, s3;                                              \
            fmul2_(s0, hva.x, hva.x);                                        \
            fmul2_(s1, hva.y, hva.y);                                        \
            fmul2_(s2, hvb.x, hvb.x);                                        \
            fmul2_(s3, hvb.y, hvb.y);                                        \
            ffma2_(aA[2 * q + 0], wj0a, hva.x);                              \
            ffma2_(aA[2 * q + 1], wj0a, hva.y);                              \
            ffma2_(aA[2 * q + 0], wj1a, hvb.x);                              \
            ffma2_(aA[2 * q + 1], wj1a, hvb.y);                              \
            ffma2_(bA[2 * q + 0], ej0a, s0);                                 \
            ffma2_(bA[2 * q + 1], ej0a, s1);                                 \
            ffma2_(bA[2 * q + 0], ej1a, s2);                                 \
            ffma2_(bA[2 * q + 1], ej1a, s3);                                 \
            ffma2_(aB[2 * q + 0], wj0b, hva.x);                              \
            ffma2_(aB[2 * q + 1], wj0b, hva.y);                              \
            ffma2_(aB[2 * q + 0], wj1b, hvb.x);                              \
            ffma2_(aB[2 * q + 1], wj1b, hvb.y);                              \
            ffma2_(bB[2 * q + 0], ej0b, s0);                                 \
            ffma2_(bB[2 * q + 1], ej0b, s1);                                 \
            ffma2_(bB[2 * q + 0], ej1b, s2);                                 \
            ffma2_(bB[2 * q + 1], ej1b, s3);                                 \
        }                                                                    \
    } while (0)

__global__ void __launch_bounds__(NTH, 2)
cnf_kernel(const float* __restrict__ z, const float* __restrict__ cond,
           const float* __restrict__ W1_0, const float* __restrict__ W1_2,
           float* __restrict__ out)
{
    extern __shared__ float smraw[];
    SM* sm = reinterpret_cast<SM*>(smraw);
    const int tid  = threadIdx.x;
    const int lane = tid & 31;
    const int wrp  = tid >> 5;
    const int i    = tid & 127;       // neuron (layer0 / reduce mapping)
    const int hs   = tid >> 7;        // sample half (q group), 0..1
    const int nb   = wrp & 1;         // layer-1 neuron block (64 neurons)
    const int jp   = wrp >> 1;        // layer-1 j partition (0..3, 32 j each)
    const int il1  = nb * 64 + lane;  // layer-1 neuron A (B = +32)
    const int s0   = blockIdx.x * SPB;

    // --- weights into smem ---
    for (int idx = tid; idx < WID * LDIM; idx += NTH) {
        int r = idx >> 4, j = idx & 15;
        sm->Wt0y[j][r] = W1_0[r * (LDIM + CDIM) + j];
    }
    for (int idx = tid; idx < LDIM * WID; idx += NTH) {
        int k = idx >> 7, r = idx & 127;
        sm->Wt2[r][k] = W1_2[idx];
    }
    // --- per-sample state + initial stage input (t=1: x = z) ---
    if (tid < SPB * LDIM) {                   // 128 threads
        int s = tid >> 4, l = tid & 15;
        float zv = z[(s0 + s) * LDIM + l];
        sm->yb[l][s] = zv;
        sm->ya[l][s] = 0.0f;
        sm->x[s >> 2][l * 4 + (s & 3)] = zv;
    }
    if (tid < SPB) sm->dlp[tid] = 0.0f;

    // --- stage-invariant condition term for layer 0, kept in registers ---
    float cacc0 = 0.0f, cacc1 = 0.0f, cacc2 = 0.0f, cacc3 = 0.0f;
#pragma unroll 4
    for (int c = 0; c < CDIM; c++) {
        float w = __ldg(&W1_0[i * (LDIM + CDIM) + LDIM + c]);
        cacc0 += w * __ldg(&cond[(s0 + hs * 4 + 0) * CDIM + c]);
        cacc1 += w * __ldg(&cond[(s0 + hs * 4 + 1) * CDIM + c]);
        cacc2 += w * __ldg(&cond[(s0 + hs * 4 + 2) * CDIM + c]);
        cacc3 += w * __ldg(&cond[(s0 + hs * 4 + 3) * CDIM + c]);
    }
    const u64 ct0 = pack2_(cacc0, cacc1);
    const u64 ct1 = pack2_(cacc2, cacc3);
    __syncthreads();

    const float dt  = -0.125f;
    const float dt6 = dt * (1.0f / 6.0f);

    for (int e = 0; e < 4 * NSTEPS; e++) {
        const int step = e >> 2, st = e & 3;
        const int   m   = 2 * step + ((st == 0) ? 0 : ((st == 3) ? 2 : 1));
        const float wst = (st == 1 || st == 2) ? 2.0f : 1.0f;

        // --- prefetch first table pair-rows for this stage (2 neurons) ---
        const float4* wep = &g_WE2[m][jp * 16][il1];
        float4 bufA[4], bufB[4];     // [pp*2 + neuron]
        bufA[0] = __ldg(wep);
        bufA[1] = __ldg(wep + 32);
        bufA[2] = __ldg(wep + WID);
        bufA[3] = __ldg(wep + WID + 32);

        // ----- layer 0: 16 y-cols (+ cached cond term), 4 samples/thread ---
        {
            u64 a0 = ct0, a1 = ct1;
#pragma unroll
            for (int j = 0; j < LDIM; j++) {
                float w = sm->Wt0y[j][i];
                u64 w2 = pack2_(w, w);
                const ulonglong2 xv =
                    *reinterpret_cast<const ulonglong2*>(&sm->x[hs][j * 4]);
                ffma2_(a0, w2, xv.x);
                ffma2_(a1, w2, xv.y);
            }
            const float g = g_g0[m][i], be = g_be0[m][i];
            float v0, v1, v2, v3, h;
            unpack2_(a0, v0, v1);
            unpack2_(a1, v2, v3);
            float4 hv;
            h = tanhf_(g * v0 + be); hv.x = h;
            h = tanhf_(g * v1 + be); hv.y = h;
            h = tanhf_(g * v2 + be); hv.z = h;
            h = tanhf_(g * v3 + be); hv.w = h;
            *reinterpret_cast<float4*>(&sm->h1[hs][i * 4]) = hv;
        }
        __syncthreads();

        // ----- layer 1: 32 j per warp, 2 neurons per lane, 8 samples -------
        {
            u64 aA[4], bA[4], aB[4], bB[4];
#pragma unroll
            for (int pr = 0; pr < 4; pr++) {
                aA[pr] = 0ull; bA[pr] = 0ull; aB[pr] = 0ull; bB[pr] = 0ull;
            }

#pragma unroll 1
            for (int c4 = 0; c4 < 4; c4++) {
                const int pb = c4 * 4;            // local pair base (of 16)
                bufB[0] = __ldg(wep + (pb + 2) * WID);
                bufB[1] = __ldg(wep + (pb + 2) * WID + 32);
                bufB[2] = __ldg(wep + (pb + 3) * WID);
                bufB[3] = __ldg(wep + (pb + 3) * WID + 32);

                L1_PAIR(bufA[0], bufA[1], jp * 16 + pb + 0);
                L1_PAIR(bufA[2], bufA[3], jp * 16 + pb + 1);

                if (c4 < 3) {
                    bufA[0] = __ldg(wep + (pb + 4) * WID);
                    bufA[1] = __ldg(wep + (pb + 4) * WID + 32);
                    bufA[2] = __ldg(wep + (pb + 5) * WID);
                    bufA[3] = __ldg(wep + (pb + 5) * WID + 32);
                }

                L1_PAIR(bufB[0], bufB[1], jp * 16 + pb + 2);
                L1_PAIR(bufB[2], bufB[3], jp * 16 + pb + 3);
            }
            // store partials (disjoint per warp)
#pragma unroll
            for (int pr = 0; pr < 4; pr++) {
                sm->predA[jp][pr][il1]      = aA[pr];
                sm->predA[jp][pr][il1 + 32] = aB[pr];
                sm->predB[jp][pr][il1]      = bA[pr];
                sm->predB[jp][pr][il1 + 32] = bB[pr];
            }
        }
        __syncthreads();

        // ----- reduce partitions; tanh; divergence; write h2 ---------------
        {
            float av[4] = {0.0f, 0.0f, 0.0f, 0.0f};
            float bv[4] = {0.0f, 0.0f, 0.0f, 0.0f};
#pragma unroll
            for (int p = 0; p < 4; p++) {
                float x0, x1;
                unpack2_(sm->predA[p][2 * hs + 0][i], x0, x1);
                av[0] += x0; av[1] += x1;
                unpack2_(sm->predA[p][2 * hs + 1][i], x0, x1);
                av[2] += x0; av[3] += x1;
                unpack2_(sm->predB[p][2 * hs + 0][i], x0, x1);
                bv[0] += x0; bv[1] += x1;
                unpack2_(sm->predB[p][2 * hs + 1][i], x0, x1);
                bv[2] += x0; bv[3] += x1;
            }
            const float g  = g_g1[m][i], be = g_be1[m][i];
            const float es = __ldg(&g_Es[m][i]);
            float4 hvec;
            float vdiv[4];
#pragma unroll
            for (int c = 0; c < 4; c++) {
                float h = tanhf_(g * av[c] + be);
                ((float*)&hvec)[c] = h;
                vdiv[c] = g * (1.0f - h * h) * (es - bv[c]);
            }
            *reinterpret_cast<float4*>(&sm->h2[hs][i * 4]) = hvec;
#pragma unroll
            for (int c = 0; c < 4; c++) {
                float r = vdiv[c];
                r += __shfl_xor_sync(0xffffffffu, r, 16);
                r += __shfl_xor_sync(0xffffffffu, r, 8);
                r += __shfl_xor_sync(0xffffffffu, r, 4);
                r += __shfl_xor_sync(0xffffffffu, r, 2);
                r += __shfl_xor_sync(0xffffffffu, r, 1);
                if (lane == 0) sm->wred[wrp][c] = r;
            }
        }
        __syncthreads();

        // ----- layer 2 (128->16) warp-specialized, packed sample pairs -----
        if (wrp < 4) {
            const int sp = wrp;               // sample pair s = 2sp, 2sp+1
            const int k  = lane & 15;
            const int pa = lane >> 4;         // i2 parity
            const int q  = sp >> 1;
            const int cp = sp & 1;
            u64 acc0 = 0ull, acc1 = 0ull;
#pragma unroll 8
            for (int n = 0; n < 64; n += 2) {
                int i2a = 2 * n + pa;
                int i2b = 2 * n + 2 + pa;
                float wa = sm->Wt2[i2a][k];
                float wb = sm->Wt2[i2b][k];
                u64 ha = *reinterpret_cast<const u64*>(&sm->h2[q][i2a * 4 + 2 * cp]);
                u64 hb = *reinterpret_cast<const u64*>(&sm->h2[q][i2b * 4 + 2 * cp]);
                ffma2_(acc0, pack2_(wa, wa), ha);
                ffma2_(acc1, pack2_(wb, wb), hb);
            }
            float l0, h0, l1, h1;
            unpack2_(acc0, l0, h0);
            unpack2_(acc1, l1, h1);
            float flo = l0 + l1, fhi = h0 + h1;
            flo += __shfl_xor_sync(0xffffffffu, flo, 16);
            fhi += __shfl_xor_sync(0xffffffffu, fhi, 16);
            if (lane < 16) {
                const float g = g_g2[m][k], be = g_be2[m][k];
                float f0 = g * flo + be;
                float f1 = g * fhi + be;
                const int s = 2 * sp;
                float2* yap = reinterpret_cast<float2*>(&sm->ya[k][s]);
                float2* ybp = reinterpret_cast<float2*>(&sm->yb[k][s]);
                float2 yav = *yap;
                float2 ybv = *ybp;
                yav.x += wst * f0; yav.y += wst * f1;
                if (st < 3) {
                    *yap = yav;
                    float cn = (st == 2) ? dt : 0.5f * dt;
                    float2 xv = make_float2(ybv.x + cn * f0, ybv.y + cn * f1);
                    *reinterpret_cast<float2*>(&sm->x[q][k * 4 + 2 * cp]) = xv;
                } else {
                    ybv.x += dt6 * yav.x; ybv.y += dt6 * yav.y;
                    *ybp = ybv;
                    *yap = make_float2(0.0f, 0.0f);
                    *reinterpret_cast<float2*>(&sm->x[q][k * 4 + 2 * cp]) = ybv;
                }
            }
        } else if (wrp == 4) {
            if (lane < SPB) {
                const int sb = (lane >> 2) * 4, c = lane & 3;
                float dv = sm->wred[sb + 0][c] + sm->wred[sb + 1][c] +
                           sm->wred[sb + 2][c] + sm->wred[sb + 3][c];
                sm->dlp[lane] += dt6 * wst * dv;
            }
        }
        __syncthreads();
    }

    // out = delta_logp + sum(-0.5 y^2 - 0.5 log(2pi))
    if (tid < SPB) {
        const int s = tid;
        float o = sm->dlp[s];
#pragma unroll
        for (int l = 0; l < LDIM; l++) {
            float yv = sm->yb[l][s];
            o += -0.5f * yv * yv - 0.5f * LOG2PI_F;
        }
        out[s0 + s] = o;
    }
}

// ---------------------------------------------------------------------------
extern "C" void kernel_launch(void* const* d_in, const int* in_sizes, int n_in,
                              void* d_out, int out_size)
{
    (void)in_sizes; (void)n_in; (void)out_size;
    const float* W1_0 = (const float*)d_in[0];
    const float* b1_0 = (const float*)d_in[1];
    const float* W2_0 = (const float*)d_in[2];
    const float* b2_0 = (const float*)d_in[3];
    const float* W3_0 = (const float*)d_in[4];
    const float* W1_1 = (const float*)d_in[5];
    const float* b1_1 = (const float*)d_in[6];
    const float* W2_1 = (const float*)d_in[7];
    const float* b2_1 = (const float*)d_in[8];
    const float* W3_1 = (const float*)d_in[9];
    const float* W1_2 = (const float*)d_in[10];
    const float* b1_2 = (const float*)d_in[11];
    const float* W2_2 = (const float*)d_in[12];
    const float* b2_2 = (const float*)d_in[13];
    const float* W3_2 = (const float*)d_in[14];
    const float* z    = (const float*)d_in[15];
    const float* cnd  = (const float*)d_in[16];
    float* out = (float*)d_out;

    cudaFuncSetAttribute(cnf_kernel, cudaFuncAttributeMaxDynamicSharedMemorySize,
                         (int)sizeof(SM));

    prep_kernel<<<NT, 1024>>>(W1_0, b1_0, W2_0, b2_0, W3_0,
                              W1_1, b1_1, W2_1, b2_1, W3_1,
                              W1_2, b1_2, W2_2, b2_2, W3_2);

    cnf_kernel<<<BATCH / SPB, NTH, sizeof(SM)>>>(z, cnd, W1_0, W1_2, out);
}